// round 17
// baseline (speedup 1.0000x reference)
#include <cuda_runtime.h>
#include <cuda_fp16.h>
#include <cstdint>

#define NDIM   512
#define BK     32
#define NCH    (NDIM / BK)          // 16
#define NSUP   (NCH / 2)            // 8 superchunks (64 k each)
#define CTA_M  128
#define CTA_N  128
#define NTHREADS 512
#define ROWB   80                   // padded smem row stride (32 fp16 = 64B + 16B pad)
#define TILEB  (128 * ROWB)         // 10240 B
#define SST_BYTES (4 * TILEB)       // superstage: A0 B0 A1 B1 = 40960
#define NSST   3
#define SMEM_STAGES (NSST * SST_BYTES)        // 122880
#define FIX_OFF     SMEM_STAGES
#define FIXLIST_OFF (SMEM_STAGES + 16)
#define CTA_FIXCAP  1024
#define SMEM_TOTAL  (FIXLIST_OFF + CTA_FIXCAP * 4)   // 126992
#define THRESH 1e-3f
#define MMAX   32768

// ---- device scratch ----
__device__ float  g_WT [NDIM * NDIM];            // W^T (n,k), diag=0, fp32 (fixup)
__device__ __half g_Whf[NDIM * NDIM];            // W^T fp16
__device__ __half g_Xh [(size_t)MMAX * NDIM];    // X fp16

__device__ __forceinline__ uint32_t smem_u32(const void* p) {
    uint32_t a;
    asm("{ .reg .u64 t; cvta.to.shared.u64 t, %1; cvt.u32.u64 %0, t; }" : "=r"(a) : "l"(p));
    return a;
}
__device__ __forceinline__ void mma_fp16(float* c, const uint32_t* a,
                                         uint32_t b0, uint32_t b1) {
    asm volatile(
        "mma.sync.aligned.m16n8k16.row.col.f32.f16.f16.f32 "
        "{%0,%1,%2,%3}, {%4,%5,%6,%7}, {%8,%9}, {%0,%1,%2,%3};\n"
        : "+f"(c[0]), "+f"(c[1]), "+f"(c[2]), "+f"(c[3])
        : "r"(a[0]), "r"(a[1]), "r"(a[2]), "r"(a[3]), "r"(b0), "r"(b1));
}
__device__ __forceinline__ void ldmx4(uint32_t* r, uint32_t addr) {
    asm volatile("ldmatrix.sync.aligned.m8n8.x4.shared.b16 {%0,%1,%2,%3}, [%4];"
        : "=r"(r[0]), "=r"(r[1]), "=r"(r[2]), "=r"(r[3]) : "r"(addr));
}
#define CP16(dst, src) \
    asm volatile("cp.async.cg.shared.global [%0], [%1], 16;\n" :: "r"(dst), "l"(src))
#define CP_COMMIT()  asm volatile("cp.async.commit_group;\n" ::: "memory")
#define CP_WAITG(n)  asm volatile("cp.async.wait_group %0;\n" :: "n"(n) : "memory")

__device__ __forceinline__ uint32_t u32of(__half2 h) {
    return *reinterpret_cast<uint32_t*>(&h);
}

// ============================ fused prep ============================
__global__ void prep_all(const float* __restrict__ W,
                         const float* __restrict__ X, int total4) {
    if (blockIdx.x < 256) {
        __shared__ float tile[32][33];
        const int k0 = (blockIdx.x & 15) * 32, n0 = (blockIdx.x >> 4) * 32;
        const int tx = threadIdx.x & 31, ty = threadIdx.x >> 5;
        #pragma unroll
        for (int j = 0; j < 32; j += 8) {
            const int k = k0 + ty + j, n = n0 + tx;
            tile[ty + j][tx] = (k == n) ? 0.0f : W[k * NDIM + n];
        }
        __syncthreads();
        #pragma unroll
        for (int j = 0; j < 32; j += 8) {
            const int n = n0 + ty + j, k = k0 + tx;
            const float w = tile[tx][ty + j];
            g_WT [n * NDIM + k] = w;
            g_Whf[n * NDIM + k] = __float2half_rn(w);
        }
    } else {
        const int idx = (blockIdx.x - 256) * blockDim.x + threadIdx.x;
        if (idx >= total4) return;
        float4 v = reinterpret_cast<const float4*>(X)[idx];
        __half2 h01 = __floats2half2_rn(v.x, v.y);
        __half2 h23 = __floats2half2_rn(v.z, v.w);
        reinterpret_cast<uint2*>(g_Xh)[idx] = make_uint2(u32of(h01), u32of(h23));
    }
}

// ============================ main (GEMM + gate + in-CTA fixup) ============================
__global__ __launch_bounds__(NTHREADS, 1)
void li_mma_kernel(const float* __restrict__ X,
                   const float* __restrict__ bias,
                   float* __restrict__ out)
{
    extern __shared__ char smem[];
    const uint32_t sb = smem_u32(smem);
    const int tid = threadIdx.x;
    const int lid = tid & 31;
    const int wid = tid >> 5;          // 0..15
    const int wm  = wid >> 2;          // 0..3 -> m offset 32
    const int wn  = wid & 3;           // 0..3 -> n offset 32
    const int g   = lid >> 2;          // 0..7
    const int t   = lid & 3;           // 0..3
    const int q   = lid >> 3;          // 0..3
    const int rl  = lid & 7;           // 0..7
    const int cta_n = blockIdx.x * CTA_N;
    const size_t cta_m = (size_t)blockIdx.y * CTA_M;

    unsigned int* fixcnt  = reinterpret_cast<unsigned int*>(smem + FIX_OFF);
    unsigned int* fixlist = reinterpret_cast<unsigned int*>(smem + FIXLIST_OFF);
    if (tid == 0) *fixcnt = 0;

    float acc[2][4][4];
    #pragma unroll
    for (int a = 0; a < 2; ++a)
        #pragma unroll
        for (int b = 0; b < 4; ++b)
            #pragma unroll
            for (int c = 0; c < 4; ++c) acc[a][b][c] = 0.0f;

    // superstage s holds chunks 2s (par 0) and 2s+1 (par 1):
    // layout [A0|B0|A1|B1], each TILEB
    const int row = tid >> 2, c4 = tid & 3;
    const uint32_t doff = row * ROWB + c4 * 16;

    auto loadSuper = [&](int s) {
        const uint32_t st = sb + (uint32_t)(s % NSST) * SST_BYTES;
        const char* xh = (const char*)g_Xh;
        const char* wh = (const char*)g_Whf;
        #pragma unroll
        for (int par = 0; par < 2; ++par) {
            const int chunk = 2 * s + par;
            size_t gA = ((cta_m + row) * NDIM + (size_t)chunk * BK) * 2 + c4 * 16;
            size_t gB = (((size_t)cta_n + row) * NDIM + (size_t)chunk * BK) * 2 + c4 * 16;
            const uint32_t pbase = st + (uint32_t)par * (2 * TILEB);
            CP16(pbase + doff,         xh + gA);
            CP16(pbase + TILEB + doff, wh + gB);
        }
        CP_COMMIT();
    };

    auto compute = [&](int chunk) {
        const uint32_t st = sb + (uint32_t)((chunk >> 1) % NSST) * SST_BYTES
                               + (uint32_t)(chunk & 1) * (2 * TILEB);
        #pragma unroll
        for (int ks = 0; ks < 2; ++ks) {
            uint32_t bh[4][2];
            #pragma unroll
            for (int ntp = 0; ntp < 2; ++ntp) {
                uint32_t baddr = st + TILEB
                    + (uint32_t)(wn * 32 + (ntp * 2 + (q >> 1)) * 8 + rl) * ROWB
                    + ks * 32 + (q & 1) * 16;
                uint32_t rr[4];
                ldmx4(rr, baddr);
                bh[2 * ntp][0] = rr[0]; bh[2 * ntp][1] = rr[1];
                bh[2 * ntp + 1][0] = rr[2]; bh[2 * ntp + 1][1] = rr[3];
            }
            #pragma unroll
            for (int mt = 0; mt < 2; ++mt) {
                uint32_t aaddr = st
                    + (uint32_t)(wm * 32 + mt * 16 + (q & 1) * 8 + rl) * ROWB
                    + ks * 32 + (q >> 1) * 16;
                uint32_t Ah[4];
                ldmx4(Ah, aaddr);
                #pragma unroll
                for (int nt = 0; nt < 4; ++nt)
                    mma_fp16(acc[mt][nt], Ah, bh[nt][0], bh[nt][1]);
            }
        }
    };

    // ---- 3-superstage pipeline: ONE barrier per 64-k superchunk ----
    loadSuper(0); loadSuper(1);
    for (int s = 0; s < NSUP; ++s) {
        if (s + 1 < NSUP) { CP_WAITG(1); } else { CP_WAITG(0); }
        __syncthreads();            // all warps past pair s-1 -> stage (s-1)%3 free
        if (s + 2 < NSUP) loadSuper(s + 2);   // writes stage (s+2)%3 == (s-1)%3
        compute(2 * s);
        compute(2 * s + 1);
    }

    // ---- epilogue: bias + gate; flag tiny |inhib| into CTA-local worklist ----
    #pragma unroll
    for (int mt = 0; mt < 2; ++mt) {
        #pragma unroll
        for (int nt = 0; nt < 4; ++nt) {
            const int gcol = cta_n + wn * 32 + nt * 8 + 2 * t;
            const float b0 = bias[gcol], b1 = bias[gcol + 1];
            #pragma unroll
            for (int half = 0; half < 2; ++half) {
                const size_t grow = cta_m + wm * 32 + mt * 16 + g + half * 8;
                const float v0 = acc[mt][nt][half * 2 + 0] + b0;
                const float v1 = acc[mt][nt][half * 2 + 1] + b1;
                if (fabsf(v0) < THRESH) {
                    unsigned int s = atomicAdd(fixcnt, 1u);
                    if (s < CTA_FIXCAP) fixlist[s] = (unsigned int)(grow * NDIM + gcol);
                }
                if (fabsf(v1) < THRESH) {
                    unsigned int s = atomicAdd(fixcnt, 1u);
                    if (s < CTA_FIXCAP) fixlist[s] = (unsigned int)(grow * NDIM + gcol + 1);
                }
                const float2 xv = *reinterpret_cast<const float2*>(
                    X + grow * NDIM + gcol);
                float2 o;
                o.x = v0 > 0.0f ? xv.x : 0.0f;
                o.y = v1 > 0.0f ? xv.y : 0.0f;
                *reinterpret_cast<float2*>(out + grow * NDIM + gcol) = o;
            }
        }
    }

    // ---- in-CTA fixup: exact fp32 dot per flagged element (one warp each) ----
    __syncthreads();
    const unsigned int cnt = min(*fixcnt, (unsigned int)CTA_FIXCAP);
    for (unsigned int j = (unsigned int)wid; j < cnt; j += (NTHREADS / 32)) {
        const unsigned int e = fixlist[j];
        const unsigned int erow = e >> 9;
        const unsigned int col = e & (NDIM - 1);
        const float4* xr = reinterpret_cast<const float4*>(X + (size_t)erow * NDIM);
        const float4* wr = reinterpret_cast<const float4*>(g_WT + (size_t)col * NDIM);
        float s = 0.0f;
        #pragma unroll
        for (int k = 0; k < NDIM / 128; ++k) {
            const float4 xv = xr[k * 32 + lid];
            const float4 wv = wr[k * 32 + lid];
            s = fmaf(xv.x, wv.x, s);
            s = fmaf(xv.y, wv.y, s);
            s = fmaf(xv.z, wv.z, s);
            s = fmaf(xv.w, wv.w, s);
        }
        #pragma unroll
        for (int off = 16; off > 0; off >>= 1)
            s += __shfl_xor_sync(0xFFFFFFFF, s, off);
        if (lid == 0) {
            const float v = s + bias[col];
            out[(size_t)e] = v > 0.0f ? X[(size_t)erow * NDIM + col] : 0.0f;
        }
    }
}

// ============================ host ============================
extern "C" void kernel_launch(void* const* d_in, const int* in_sizes, int n_in,
                              void* d_out, int out_size)
{
    const float* X    = (const float*)d_in[0];
    const float* W    = (const float*)d_in[1];
    const float* bias = (const float*)d_in[2];
    float* out = (float*)d_out;
    const int M = in_sizes[0] / NDIM;   // 32768

    const int total4 = M * NDIM / 4;                 // 4,194,304
    const int xblocks = (total4 + 255) / 256;        // 16384
    prep_all<<<256 + xblocks, 256>>>(W, X, total4);

    cudaFuncSetAttribute(li_mma_kernel,
                         cudaFuncAttributeMaxDynamicSharedMemorySize, SMEM_TOTAL);
    dim3 grid(NDIM / CTA_N, M / CTA_M);   // (4, 256)
    li_mma_kernel<<<grid, NTHREADS, SMEM_TOTAL>>>(X, bias, out);
}